// round 2
// baseline (speedup 1.0000x reference)
#include <cuda_runtime.h>
#include <cstddef>

// Problem constants
#define BB   2048
#define TT   512
#define D_IN 4
#define HH   64
#define LL   4
#define OUTN 5
#define G4   256   // 4*H

// -------------------------- device scratch --------------------------------
__device__ float g_hsA[(size_t)TT * BB * HH];   // 256 MB ping
__device__ float g_hsB[(size_t)TT * BB * HH];   // 256 MB pong
// Pair-layout weights per layer: float4 index ((k>>1)*2+gp)*64+u holds
// {g0(2k2), g1(2k2), g0(2k2+1), g1(2k2+1)}, gp=0 -> gates (u, 64+u) = (i,f),
// gp=1 -> gates (128+u, 192+u) = (g,o).
__device__ float g_Wp[LL][32768];               // 128KB/layer max (KPAD=128)
__device__ float g_bias[LL][G4];

// -------------------------- f32x2 helpers ---------------------------------
#define FFMA2(d, a, b, c) \
    asm("fma.rn.f32x2 %0, %1, %2, %3;" : "=l"(d) : "l"(a), "l"(b), "l"(c))
#define FADD2(d, a, b) \
    asm("add.rn.f32x2 %0, %1, %2;" : "=l"(d) : "l"(a), "l"(b))

union U2F2 { unsigned long long u; float2 f; };

__device__ __forceinline__ float sigf(float x) {
    return __fdividef(1.0f, 1.0f + __expf(-x));
}
__device__ __forceinline__ float tanhg(float x) {
    return __fdividef(2.0f, 1.0f + __expf(-2.0f * x)) - 1.0f;
}

// ---------------------------------------------------------------------------
// Weight prep: scatter into FFMA2 pair layout (+zero K padding) and fuse bias.
// ---------------------------------------------------------------------------
__global__ void prep_kernel(const float* __restrict__ W_ih0,
                            const float* __restrict__ W_ihr,
                            const float* __restrict__ W_hh,
                            const float* __restrict__ b_ih,
                            const float* __restrict__ b_hh) {
    int idx = blockIdx.x * blockDim.x + threadIdx.x;   // l*256*128 + gate*128 + k
    if (idx >= LL * G4 * 128) return;
    int k    = idx & 127;
    int gate = (idx >> 7) & 255;
    int l    = idx >> 15;

    int KPAD = (l == 0) ? 80 : 128;
    if (k >= KPAD) { if (k == 127) {} return; }

    float v;
    if (l == 0) {
        if (k < D_IN)            v = W_ih0[gate * D_IN + k];
        else if (k < D_IN + HH)  v = W_hh[gate * HH + (k - D_IN)];     // layer 0
        else                     v = 0.0f;                              // pad
    } else {
        if (k < HH) v = W_ihr[((size_t)(l - 1) * G4 + gate) * HH + k];
        else        v = W_hh[((size_t)l * G4 + gate) * HH + (k - HH)];
    }

    int q    = gate >> 6;       // 0..3
    int u    = gate & 63;
    int gp   = q >> 1;          // gate-pair
    int half = q & 1;           // position within pair
    int fidx = ((((k >> 1) * 2 + gp) * 64 + u) << 2) + ((k & 1) << 1) + half;
    g_Wp[l][fidx] = v;

    if (k == 0)
        g_bias[l][gate] = b_ih[l * G4 + gate] + b_hh[l * G4 + gate];
}

// ---------------------------------------------------------------------------
// Persistent per-layer LSTM, FFMA2 + k-split-4.
//   256 threads: u = tid&63 (unit), kq = tid>>6 (k-quarter; fixed per warp).
//   GEMM: thread computes partials for ALL 16 rows, its 2 gate-pairs of unit
//   u, over k in [kq*KQ, (kq+1)*KQ). 4-way reduction via SMEM (skip own rows:
//   epilogue thread reuses kq as its row-group rq).
//   SMEM: Ws (pair layout) | Ad (A duplicated {a,a}, [row][k] float2) | Red.
// ---------------------------------------------------------------------------
template <int KIN, int KPAD>
__global__ void __launch_bounds__(256, 1)
lstm_layer(const float* __restrict__ in, int layer, float* __restrict__ ouths) {
    constexpr int K2T = KPAD / 2;    // total k2 (k-pairs)
    constexpr int K2Q = KPAD / 8;    // k2 per k-quarter

    extern __shared__ float smem[];
    float*              Ws  = smem;                                   // KPAD*256 floats
    float2*             Ad  = (float2*)(smem + KPAD * 256);           // [16][KPAD]
    unsigned long long* Red = (unsigned long long*)(Ad + 16 * KPAD);  // [4][16][2][64]

    const int tid     = threadIdx.x;
    const int u       = tid & 63;
    const int kq      = tid >> 6;
    const int rowbase = blockIdx.x * 16;

    // Load pair-layout weights (contiguous copy)
    {
        const float4* src = (const float4*)g_Wp[layer];
        float4*       dst = (float4*)Ws;
        for (int i = tid; i < KPAD * 64; i += 256) dst[i] = src[i];
    }
    // Zero Ad (h=0 initial state + zero K padding)
    for (int i = tid; i < 16 * KPAD; i += 256) Ad[i] = make_float2(0.f, 0.f);
    __syncthreads();

    const float bi = g_bias[layer][u];
    const float bf = g_bias[layer][64 + u];
    const float bg = g_bias[layer][128 + u];
    const float bo = g_bias[layer][192 + u];
    float c[4] = {0.f, 0.f, 0.f, 0.f};

    // Stage x(0)
    if (KIN == 4) {
        if (tid < 64) {
            int r = tid >> 2, j = tid & 3;
            float v = in[(size_t)(rowbase + r) * (TT * D_IN) + j];
            Ad[r * KPAD + j] = make_float2(v, v);
        }
    } else {
        int r  = tid >> 4;
        int kk = (tid & 15) * 4;
        float4 v = *(const float4*)&in[(size_t)(rowbase + r) * HH + kk];
        Ad[r * KPAD + kk + 0] = make_float2(v.x, v.x);
        Ad[r * KPAD + kk + 1] = make_float2(v.y, v.y);
        Ad[r * KPAD + kk + 2] = make_float2(v.z, v.z);
        Ad[r * KPAD + kk + 3] = make_float2(v.w, v.w);
    }
    __syncthreads();

    const ulonglong2* Wp4 = (const ulonglong2*)Ws;
    const ulonglong2* Ad4 = (const ulonglong2*)Ad;
    const int k2beg = kq * K2Q;

    for (int t = 0; t < TT; ++t) {
        // ---- GEMM partials: acc[row][gp] (f32x2 pairs), k in this quarter ----
        unsigned long long acc[16][2];
        #pragma unroll
        for (int r = 0; r < 16; r++) { acc[r][0] = 0ull; acc[r][1] = 0ull; }

        #pragma unroll 2
        for (int k2 = k2beg; k2 < k2beg + K2Q; ++k2) {
            ulonglong2 w0 = Wp4[(k2 * 2 + 0) * 64 + u];   // (i,f) pairs, k even/odd
            ulonglong2 w1 = Wp4[(k2 * 2 + 1) * 64 + u];   // (g,o) pairs
            #pragma unroll
            for (int r = 0; r < 16; r++) {
                ulonglong2 a = Ad4[r * K2T + k2];         // {a(2k2) dup, a(2k2+1) dup}
                FFMA2(acc[r][0], a.x, w0.x, acc[r][0]);
                FFMA2(acc[r][1], a.x, w1.x, acc[r][1]);
                FFMA2(acc[r][0], a.y, w0.y, acc[r][0]);
                FFMA2(acc[r][1], a.y, w1.y, acc[r][1]);
            }
        }

        // ---- publish partials (skip rows this thread epilogues itself) ----
        #pragma unroll
        for (int r = 0; r < 16; r++) {
            if ((r & 3) != kq) {
                Red[((kq * 16 + r) * 2 + 0) * 64 + u] = acc[r][0];
                Red[((kq * 16 + r) * 2 + 1) * 64 + u] = acc[r][1];
            }
        }
        __syncthreads();   // partials visible; Ad reads complete

        // ---- epilogue: rows {kq, kq+4, kq+8, kq+12} for unit u ----
        #pragma unroll
        for (int rr = 0; rr < 4; rr++) {
            int row = kq + 4 * rr;
            unsigned long long s0 = acc[row][0], s1 = acc[row][1];
            #pragma unroll
            for (int oq = 0; oq < 4; oq++) {
                if (oq != kq) {
                    unsigned long long p0 = Red[((oq * 16 + row) * 2 + 0) * 64 + u];
                    unsigned long long p1 = Red[((oq * 16 + row) * 2 + 1) * 64 + u];
                    FADD2(s0, s0, p0);
                    FADD2(s1, s1, p1);
                }
            }
            U2F2 vif, vgo;
            vif.u = s0; vgo.u = s1;
            float gi = sigf(vif.f.x + bi);
            float gf = sigf(vif.f.y + bf);
            float gg = tanhg(vgo.f.x + bg);
            float go = sigf(vgo.f.y + bo);
            float cn = gf * c[rr] + gi * gg;
            c[rr] = cn;
            float hn = go * tanhg(cn);
            Ad[row * KPAD + KIN + u] = make_float2(hn, hn);   // feedback (dup)
            ouths[(size_t)t * (BB * HH) + (size_t)(rowbase + row) * HH + u] = hn;
        }

        // ---- stage x(t+1) (disjoint Ad columns; GEMM(t) reads are done) ----
        if (t + 1 < TT) {
            if (KIN == 4) {
                if (tid < 64) {
                    int r = tid >> 2, j = tid & 3;
                    float v = in[(size_t)(rowbase + r) * (TT * D_IN) +
                                 (t + 1) * D_IN + j];
                    Ad[r * KPAD + j] = make_float2(v, v);
                }
            } else {
                int r  = tid >> 4;
                int kk = (tid & 15) * 4;
                float4 v = *(const float4*)&in[(size_t)(t + 1) * (BB * HH) +
                                               (size_t)(rowbase + r) * HH + kk];
                Ad[r * KPAD + kk + 0] = make_float2(v.x, v.x);
                Ad[r * KPAD + kk + 1] = make_float2(v.y, v.y);
                Ad[r * KPAD + kk + 2] = make_float2(v.z, v.z);
                Ad[r * KPAD + kk + 3] = make_float2(v.w, v.w);
            }
        }
        __syncthreads();   // h + x(t+1) visible before next GEMM
    }
}

// ---------------------------------------------------------------------------
// Final FC on last timestep of top layer.
// ---------------------------------------------------------------------------
__global__ void fc_kernel(const float* __restrict__ hs,
                          const float* __restrict__ Wfc,
                          const float* __restrict__ bfc,
                          float* __restrict__ out) {
    int idx = blockIdx.x * blockDim.x + threadIdx.x;
    if (idx >= BB * OUTN) return;
    int b = idx / OUTN, o = idx - b * OUTN;
    const float* h = &hs[(size_t)(TT - 1) * (BB * HH) + (size_t)b * HH];
    float s = bfc[o];
    #pragma unroll
    for (int j = 0; j < HH; j++) s = fmaf(h[j], Wfc[o * HH + j], s);
    out[idx] = s;
}

// ---------------------------------------------------------------------------
extern "C" void kernel_launch(void* const* d_in, const int* in_sizes, int n_in,
                              void* d_out, int out_size) {
    const float* x     = (const float*)d_in[0];
    const float* W_ih0 = (const float*)d_in[1];
    const float* W_ihr = (const float*)d_in[2];
    const float* W_hh  = (const float*)d_in[3];
    const float* b_ih  = (const float*)d_in[4];
    const float* b_hh  = (const float*)d_in[5];
    const float* W_fc  = (const float*)d_in[6];
    const float* b_fc  = (const float*)d_in[7];
    float* out = (float*)d_out;

    float *hsA = nullptr, *hsB = nullptr;
    cudaGetSymbolAddress((void**)&hsA, g_hsA);
    cudaGetSymbolAddress((void**)&hsB, g_hsB);

    // SMEM: Ws (KPAD*256*4) + Ad (16*KPAD*8) + Red (4*16*2*64*8 = 65536)
    constexpr int SMEM_L0 = 80  * 256 * 4 + 16 * 80  * 8 + 65536;  // 157,696 B
    constexpr int SMEM_LN = 128 * 256 * 4 + 16 * 128 * 8 + 65536;  // 212,992 B
    cudaFuncSetAttribute(lstm_layer<4, 80>,
                         cudaFuncAttributeMaxDynamicSharedMemorySize, SMEM_L0);
    cudaFuncSetAttribute(lstm_layer<64, 128>,
                         cudaFuncAttributeMaxDynamicSharedMemorySize, SMEM_LN);

    prep_kernel<<<LL * G4 * 128 / 256, 256>>>(W_ih0, W_ihr, W_hh, b_ih, b_hh);

    lstm_layer<4, 80><<<BB / 16, 256, SMEM_L0>>>(x, 0, hsA);
    lstm_layer<64, 128><<<BB / 16, 256, SMEM_LN>>>(hsA, 1, hsB);
    lstm_layer<64, 128><<<BB / 16, 256, SMEM_LN>>>(hsB, 2, hsA);
    lstm_layer<64, 128><<<BB / 16, 256, SMEM_LN>>>(hsA, 3, hsB);

    fc_kernel<<<(BB * OUTN + 255) / 256, 256>>>(hsB, W_fc, b_fc, out);
}

// round 3
// speedup vs baseline: 1.2752x; 1.2752x over previous
#include <cuda_runtime.h>
#include <cstddef>

// Problem constants
#define BB   2048
#define TT   512
#define D_IN 4
#define HH   64
#define LL   4
#define OUTN 5
#define G4   256   // 4*H

// -------------------------- device scratch --------------------------------
__device__ float g_hsA[(size_t)TT * BB * HH];   // 256 MB ping
__device__ float g_hsB[(size_t)TT * BB * HH];   // 256 MB pong
// Pair-layout weights: float index (((k>>1)*2+gp)*64+u)*4 + (k&1)*2 + half
// holds gate (gp*128 + half*64 + u) at k.  gp=0 -> (i,f), gp=1 -> (g,o).
__device__ float g_Wp[LL][32768];
__device__ float g_bias[LL][G4];

// -------------------------- f32x2 helpers ---------------------------------
#define FFMA2(d, a, b, c) \
    asm("fma.rn.f32x2 %0, %1, %2, %3;" : "=l"(d) : "l"(a), "l"(b), "l"(c))
#define FADD2(d, a, b) \
    asm("add.rn.f32x2 %0, %1, %2;" : "=l"(d) : "l"(a), "l"(b))

union U2F2 { unsigned long long u; float2 f; };

__device__ __forceinline__ float sigf(float x) {
    return __fdividef(1.0f, 1.0f + __expf(-x));
}
__device__ __forceinline__ float tanhg(float x) {
    return __fdividef(2.0f, 1.0f + __expf(-2.0f * x)) - 1.0f;
}

// ---------------------------------------------------------------------------
// Weight prep: scatter into FFMA2 gate-pair layout, fuse bias.
// Layer 0: K = 68 (4 input + 64 hidden), layers 1-3: K = 128.
// ---------------------------------------------------------------------------
__global__ void prep_kernel(const float* __restrict__ W_ih0,
                            const float* __restrict__ W_ihr,
                            const float* __restrict__ W_hh,
                            const float* __restrict__ b_ih,
                            const float* __restrict__ b_hh) {
    int idx = blockIdx.x * blockDim.x + threadIdx.x;   // l*256*128 + gate*128 + k
    if (idx >= LL * G4 * 128) return;
    int k    = idx & 127;
    int gate = (idx >> 7) & 255;
    int l    = idx >> 15;

    if (k == 0)
        g_bias[l][gate] = b_ih[l * G4 + gate] + b_hh[l * G4 + gate];

    int K = (l == 0) ? (D_IN + HH) : 128;
    if (k >= K) return;

    float v;
    if (l == 0) {
        if (k < D_IN) v = W_ih0[gate * D_IN + k];
        else          v = W_hh[gate * HH + (k - D_IN)];
    } else {
        if (k < HH) v = W_ihr[((size_t)(l - 1) * G4 + gate) * HH + k];
        else        v = W_hh[((size_t)l * G4 + gate) * HH + (k - HH)];
    }

    int q    = gate >> 6;       // 0..3 (i,f,g,o blocks)
    int u    = gate & 63;
    int gp   = q >> 1;          // gate-pair: 0=(i,f), 1=(g,o)
    int half = q & 1;
    int fidx = ((((k >> 1) * 2 + gp) * 64 + u) << 2) + ((k & 1) << 1) + half;
    g_Wp[l][fidx] = v;
}

// ---------------------------------------------------------------------------
// Persistent per-layer LSTM, gate-pair FFMA2, R1 structure.
//   256 threads: u = tid&63 (unit), rq = tid>>6; thread owns rows rq+4rr.
//   Warp lanes share rq -> A loads broadcast; W pair layout is u-contiguous
//   16B elements -> conflict-free LDS.128.
//   SMEM: Wp (K*256 floats, pair layout) | Ad (A duplicated {a,a}, [16][K]).
// ---------------------------------------------------------------------------
template <int KIN, bool WRITE_ALL>
__global__ void __launch_bounds__(256, 1)
lstm_layer(const float* __restrict__ in, int layer, float* __restrict__ ouths) {
    constexpr int K   = KIN + HH;    // 68 or 128 (both multiples of 4)
    constexpr int AK2 = K / 2;       // ulonglong2 per A row

    extern __shared__ float smem[];
    float*  Ws = smem;                          // K * 256 floats (pair layout)
    float2* Ad = (float2*)(smem + K * 256);     // [16][K] duplicated A

    const int tid     = threadIdx.x;
    const int u       = tid & 63;
    const int rq      = tid >> 6;
    const int rowbase = blockIdx.x * 16;

    // Load pair-layout weights (contiguous copy)
    {
        const float4* src = (const float4*)g_Wp[layer];
        float4*       dst = (float4*)Ws;
        for (int i = tid; i < K * 64; i += 256) dst[i] = src[i];
    }
    // Zero Ad (h = 0 initial state)
    for (int i = tid; i < 16 * K; i += 256) Ad[i] = make_float2(0.f, 0.f);
    __syncthreads();

    // Bias pairs
    U2F2 bif, bgo;
    bif.f = make_float2(g_bias[layer][u],       g_bias[layer][64 + u]);
    bgo.f = make_float2(g_bias[layer][128 + u], g_bias[layer][192 + u]);
    float c[4] = {0.f, 0.f, 0.f, 0.f};

    // Stage x(0)
    if (KIN == 4) {
        if (tid < 64) {
            int r = tid >> 2, j = tid & 3;
            float v = in[(size_t)(rowbase + r) * (TT * D_IN) + j];
            Ad[r * K + j] = make_float2(v, v);
        }
    } else {
        int r  = tid >> 4;
        int kk = (tid & 15) * 4;
        float4 v = *(const float4*)&in[(size_t)(rowbase + r) * HH + kk];
        Ad[r * K + kk + 0] = make_float2(v.x, v.x);
        Ad[r * K + kk + 1] = make_float2(v.y, v.y);
        Ad[r * K + kk + 2] = make_float2(v.z, v.z);
        Ad[r * K + kk + 3] = make_float2(v.w, v.w);
    }
    __syncthreads();

    const ulonglong2* Wp4 = (const ulonglong2*)Ws;
    const ulonglong2* Ad2 = (const ulonglong2*)Ad;

    for (int t = 0; t < TT; ++t) {
        // ---- GEMM: accIF/accGO[rr] f32x2 over K ----
        unsigned long long accIF[4], accGO[4];
        #pragma unroll
        for (int rr = 0; rr < 4; rr++) { accIF[rr] = 0ull; accGO[rr] = 0ull; }

        #pragma unroll 4
        for (int k2 = 0; k2 < AK2; k2 += 2) {   // 4 k per iteration
            ulonglong2 w0 = Wp4[(k2 * 2 + 0) * 64 + u];       // (i,f) k0,k1
            ulonglong2 w1 = Wp4[(k2 * 2 + 1) * 64 + u];       // (g,o) k0,k1
            ulonglong2 w2 = Wp4[((k2 + 1) * 2 + 0) * 64 + u]; // (i,f) k2,k3
            ulonglong2 w3 = Wp4[((k2 + 1) * 2 + 1) * 64 + u]; // (g,o) k2,k3
            #pragma unroll
            for (int rr = 0; rr < 4; rr++) {
                int row = rq + 4 * rr;
                ulonglong2 a01 = Ad2[row * AK2 + k2];
                ulonglong2 a23 = Ad2[row * AK2 + k2 + 1];
                FFMA2(accIF[rr], a01.x, w0.x, accIF[rr]);
                FFMA2(accGO[rr], a01.x, w1.x, accGO[rr]);
                FFMA2(accIF[rr], a01.y, w0.y, accIF[rr]);
                FFMA2(accGO[rr], a01.y, w1.y, accGO[rr]);
                FFMA2(accIF[rr], a23.x, w2.x, accIF[rr]);
                FFMA2(accGO[rr], a23.x, w3.x, accGO[rr]);
                FFMA2(accIF[rr], a23.y, w2.y, accIF[rr]);
                FFMA2(accGO[rr], a23.y, w3.y, accGO[rr]);
            }
        }
        __syncthreads();  // all GEMM reads of Ad done before overwriting

        // ---- LSTM epilogue ----
        #pragma unroll
        for (int rr = 0; rr < 4; rr++) {
            int row = rq + 4 * rr;
            unsigned long long s0, s1;
            FADD2(s0, accIF[rr], bif.u);
            FADD2(s1, accGO[rr], bgo.u);
            U2F2 vif, vgo;
            vif.u = s0; vgo.u = s1;
            float gi = sigf(vif.f.x);
            float gf = sigf(vif.f.y);
            float gg = tanhg(vgo.f.x);
            float go = sigf(vgo.f.y);
            float cn = gf * c[rr] + gi * gg;
            c[rr] = cn;
            float hn = go * tanhg(cn);
            Ad[row * K + KIN + u] = make_float2(hn, hn);   // feedback (dup)
            if (WRITE_ALL || t == TT - 1)
                ouths[(size_t)t * (BB * HH) +
                      (size_t)(rowbase + row) * HH + u] = hn;
        }

        // ---- stage x(t+1) (disjoint Ad columns) ----
        if (t + 1 < TT) {
            if (KIN == 4) {
                if (tid < 64) {
                    int r = tid >> 2, j = tid & 3;
                    float v = in[(size_t)(rowbase + r) * (TT * D_IN) +
                                 (t + 1) * D_IN + j];
                    Ad[r * K + j] = make_float2(v, v);
                }
            } else {
                int r  = tid >> 4;
                int kk = (tid & 15) * 4;
                float4 v = *(const float4*)&in[(size_t)(t + 1) * (BB * HH) +
                                               (size_t)(rowbase + r) * HH + kk];
                Ad[r * K + kk + 0] = make_float2(v.x, v.x);
                Ad[r * K + kk + 1] = make_float2(v.y, v.y);
                Ad[r * K + kk + 2] = make_float2(v.z, v.z);
                Ad[r * K + kk + 3] = make_float2(v.w, v.w);
            }
        }
        __syncthreads();   // h + x(t+1) visible before next GEMM
    }
}

// ---------------------------------------------------------------------------
// Final FC on last timestep of top layer.
// ---------------------------------------------------------------------------
__global__ void fc_kernel(const float* __restrict__ hs,
                          const float* __restrict__ Wfc,
                          const float* __restrict__ bfc,
                          float* __restrict__ out) {
    int idx = blockIdx.x * blockDim.x + threadIdx.x;
    if (idx >= BB * OUTN) return;
    int b = idx / OUTN, o = idx - b * OUTN;
    const float* h = &hs[(size_t)(TT - 1) * (BB * HH) + (size_t)b * HH];
    float s = bfc[o];
    #pragma unroll
    for (int j = 0; j < HH; j++) s = fmaf(h[j], Wfc[o * HH + j], s);
    out[idx] = s;
}

// ---------------------------------------------------------------------------
extern "C" void kernel_launch(void* const* d_in, const int* in_sizes, int n_in,
                              void* d_out, int out_size) {
    const float* x     = (const float*)d_in[0];
    const float* W_ih0 = (const float*)d_in[1];
    const float* W_ihr = (const float*)d_in[2];
    const float* W_hh  = (const float*)d_in[3];
    const float* b_ih  = (const float*)d_in[4];
    const float* b_hh  = (const float*)d_in[5];
    const float* W_fc  = (const float*)d_in[6];
    const float* b_fc  = (const float*)d_in[7];
    float* out = (float*)d_out;

    float *hsA = nullptr, *hsB = nullptr;
    cudaGetSymbolAddress((void**)&hsA, g_hsA);
    cudaGetSymbolAddress((void**)&hsB, g_hsB);

    // SMEM: W (K*256*4 B) + Ad (16*K*8 B)
    constexpr int SMEM_L0 = 68  * 256 * 4 + 16 * 68  * 8;   //  78,336 B
    constexpr int SMEM_LN = 128 * 256 * 4 + 16 * 128 * 8;   // 147,456 B
    cudaFuncSetAttribute(lstm_layer<4, true>,
                         cudaFuncAttributeMaxDynamicSharedMemorySize, SMEM_L0);
    cudaFuncSetAttribute(lstm_layer<64, true>,
                         cudaFuncAttributeMaxDynamicSharedMemorySize, SMEM_LN);
    cudaFuncSetAttribute(lstm_layer<64, false>,
                         cudaFuncAttributeMaxDynamicSharedMemorySize, SMEM_LN);

    prep_kernel<<<LL * G4 * 128 / 256, 256>>>(W_ih0, W_ihr, W_hh, b_ih, b_hh);

    lstm_layer<4,  true ><<<BB / 16, 256, SMEM_L0>>>(x,   0, hsA);
    lstm_layer<64, true ><<<BB / 16, 256, SMEM_LN>>>(hsA, 1, hsB);
    lstm_layer<64, true ><<<BB / 16, 256, SMEM_LN>>>(hsB, 2, hsA);
    lstm_layer<64, false><<<BB / 16, 256, SMEM_LN>>>(hsA, 3, hsB);

    fc_kernel<<<(BB * OUTN + 255) / 256, 256>>>(hsB, W_fc, b_fc, out);
}

// round 4
// speedup vs baseline: 1.6245x; 1.2739x over previous
#include <cuda_runtime.h>
#include <cstddef>

// Problem constants
#define BB   2048
#define TT   512
#define D_IN 4
#define HH   64
#define LL   4
#define OUTN 5
#define G4   256   // 4*H

// -------------------------- device scratch --------------------------------
__device__ float  g_hsA[(size_t)TT * BB * HH];       // 256 MB ping
__device__ float  g_hsB[(size_t)TT * BB * HH];       // 256 MB pong
__device__ float4 g_xg[(size_t)TT * BB * HH];        // 1 GB: [row][u] float4 (i,f,g,o)
__device__ float  g_W0sc[G4 * 68];                   // layer0 combined [gate][68]
__device__ float  g_Whhsc[LL][G4 * HH];              // W_hh scalar [gate][64]
__device__ float  g_Wpih[LL - 1][HH * G4];           // pair layout W_ih (layers 1-3)
__device__ float  g_bias[LL][G4];

// -------------------------- f32x2 helpers ---------------------------------
#define FFMA2(d, a, b, c) \
    asm("fma.rn.f32x2 %0, %1, %2, %3;" : "=l"(d) : "l"(a), "l"(b), "l"(c))

union U2F2 { unsigned long long u; float2 f; };

__device__ __forceinline__ float sigf(float x) {
    return __fdividef(1.0f, 1.0f + __expf(-x));
}
__device__ __forceinline__ float tanhg(float x) {
    return __fdividef(2.0f, 1.0f + __expf(-2.0f * x)) - 1.0f;
}

// ---------------------------------------------------------------------------
// Weight prep.
//   g_W0sc : layer0 [gate][0:4)=W_ih0, [4:68)=W_hh[0]
//   g_Whhsc: W_hh[l] plain [gate][64]
//   g_Wpih : layers 1-3 W_ih in FFMA2 gate-pair layout:
//            float ((((k>>1)*2+gp)*64+u)<<2) + (k&1)*2 + half
//            holds gate (gp*128 + half*64 + u) at k.
// ---------------------------------------------------------------------------
__global__ void prep_kernel(const float* __restrict__ W_ih0,
                            const float* __restrict__ W_ihr,
                            const float* __restrict__ W_hh,
                            const float* __restrict__ b_ih,
                            const float* __restrict__ b_hh) {
    int idx = blockIdx.x * blockDim.x + threadIdx.x;   // l*256*128 + gate*128 + k
    if (idx >= LL * G4 * 128) return;
    int k    = idx & 127;
    int gate = (idx >> 7) & 255;
    int l    = idx >> 15;

    if (k == 0)
        g_bias[l][gate] = b_ih[l * G4 + gate] + b_hh[l * G4 + gate];

    if (l == 0) {
        if (k < D_IN)            g_W0sc[gate * 68 + k] = W_ih0[gate * D_IN + k];
        else if (k < D_IN + HH)  g_W0sc[gate * 68 + k] = W_hh[gate * HH + (k - D_IN)];
        // also stash layer0 W_hh scalar (unused but harmless)
        if (k < HH) g_Whhsc[0][gate * HH + k] = W_hh[gate * HH + k];
    } else {
        if (k < HH) {
            // pair layout for xg GEMM
            float v  = W_ihr[((size_t)(l - 1) * G4 + gate) * HH + k];
            int q    = gate >> 6;
            int u    = gate & 63;
            int gp   = q >> 1;
            int half = q & 1;
            int fidx = ((((k >> 1) * 2 + gp) * 64 + u) << 2) + ((k & 1) << 1) + half;
            g_Wpih[l - 1][fidx] = v;
        } else {
            int kk = k - HH;  // 0..63
            g_Whhsc[l][gate * HH + kk] =
                W_hh[((size_t)l * G4 + gate) * HH + kk];
        }
    }
}

// ---------------------------------------------------------------------------
// xg GEMM (layers 1-3): xg[row][u] = float4 gate preacts (i,f,g,o) + bias.
//   A = hs [row][64] fp32, W = pair layout, FFMA2 with A duplicated in SMEM.
//   Tile: M=32 rows per CTA, 256 threads (u = tid&63, rq = tid>>6),
//   thread owns rows rq+4j (j<8) -> 16 u64 accumulators.
// ---------------------------------------------------------------------------
__global__ void __launch_bounds__(256, 2)
xg_gemm(const float* __restrict__ hs, const float* __restrict__ Wp,
        const float* __restrict__ bias, float4* __restrict__ xg) {
    extern __shared__ float smem[];
    float*  Wps = smem;                       // 64*256 floats = 64KB
    float2* Ad  = (float2*)(smem + HH * G4);  // [32][64] duplicated = 16KB

    const int    tid  = threadIdx.x;
    const size_t row0 = (size_t)blockIdx.x * 32;

    // Load W (contiguous)
    {
        const float4* src = (const float4*)Wp;
        float4*       dst = (float4*)Wps;
        #pragma unroll
        for (int i = 0; i < 16; i++) dst[tid + 256 * i] = src[tid + 256 * i];
    }
    // Load A tile, duplicate each element {a,a}
    {
        const float4* src = (const float4*)(hs + row0 * HH);
        #pragma unroll
        for (int i = tid; i < 512; i += 256) {
            float4 v = src[i];
            int row = i >> 4, kk = (i & 15) * 4;
            Ad[row * HH + kk + 0] = make_float2(v.x, v.x);
            Ad[row * HH + kk + 1] = make_float2(v.y, v.y);
            Ad[row * HH + kk + 2] = make_float2(v.z, v.z);
            Ad[row * HH + kk + 3] = make_float2(v.w, v.w);
        }
    }
    __syncthreads();

    const int u  = tid & 63;
    const int rq = tid >> 6;

    U2F2 bif, bgo;
    bif.f = make_float2(bias[u],       bias[64 + u]);
    bgo.f = make_float2(bias[128 + u], bias[192 + u]);

    unsigned long long accIF[8], accGO[8];
    #pragma unroll
    for (int j = 0; j < 8; j++) { accIF[j] = bif.u; accGO[j] = bgo.u; }

    const ulonglong2* Wp2 = (const ulonglong2*)Wps;  // (k2*2+gp)*64+u
    const ulonglong2* Ad2 = (const ulonglong2*)Ad;   // row*32+k2

    #pragma unroll 4
    for (int k2 = 0; k2 < 32; ++k2) {
        ulonglong2 w0 = Wp2[(k2 * 2 + 0) * 64 + u];   // (i,f) k even/odd
        ulonglong2 w1 = Wp2[(k2 * 2 + 1) * 64 + u];   // (g,o)
        #pragma unroll
        for (int j = 0; j < 8; j++) {
            int row = rq + 4 * j;
            ulonglong2 a = Ad2[row * 32 + k2];        // broadcast
            FFMA2(accIF[j], a.x, w0.x, accIF[j]);
            FFMA2(accGO[j], a.x, w1.x, accGO[j]);
            FFMA2(accIF[j], a.y, w0.y, accIF[j]);
            FFMA2(accGO[j], a.y, w1.y, accGO[j]);
        }
    }

    #pragma unroll
    for (int j = 0; j < 8; j++) {
        int row = rq + 4 * j;
        U2F2 vif, vgo;
        vif.u = accIF[j]; vgo.u = accGO[j];
        xg[(row0 + row) * HH + u] =
            make_float4(vif.f.x, vif.f.y, vgo.f.x, vgo.f.y);
    }
}

// ---------------------------------------------------------------------------
// Layer-0 recurrence (R1-proven): K = 68 = [x(4) | h(64)], bias in epilogue.
// ---------------------------------------------------------------------------
__global__ void __launch_bounds__(256, 1)
lstm_rec0(const float* __restrict__ in, float* __restrict__ ouths) {
    constexpr int K = 68, AW = 17;   // K/4 = 17 (odd) -> conflict-free
    extern __shared__ float smem[];
    float* Ws = smem;                // 256*68
    float* As = smem + G4 * K;       // 16*68

    const int tid     = threadIdx.x;
    const int u       = tid & 63;
    const int rq      = tid >> 6;
    const int rowbase = blockIdx.x * 16;

    for (int i = tid; i < G4 * K; i += 256) Ws[i] = g_W0sc[i];
    for (int i = tid; i < 16 * K; i += 256) As[i] = 0.0f;
    __syncthreads();

    const float bi = g_bias[0][u];
    const float bf = g_bias[0][64 + u];
    const float bg = g_bias[0][128 + u];
    const float bo = g_bias[0][192 + u];
    float c[4] = {0.f, 0.f, 0.f, 0.f};

    // stage x(0)
    if (tid < 64) {
        int r = tid >> 2, j = tid & 3;
        As[r * K + j] = in[(size_t)(rowbase + r) * (TT * D_IN) + j];
    }
    __syncthreads();

    const float4* As4 = (const float4*)As;
    const float4* Ws4 = (const float4*)Ws;

    for (int t = 0; t < TT; ++t) {
        float acc[4][4];
        #pragma unroll
        for (int q = 0; q < 4; q++)
            #pragma unroll
            for (int rr = 0; rr < 4; rr++) acc[q][rr] = 0.0f;

        #pragma unroll 4
        for (int k4 = 0; k4 < AW; ++k4) {
            float4 a[4];
            #pragma unroll
            for (int rr = 0; rr < 4; rr++) a[rr] = As4[(rq + 4 * rr) * AW + k4];
            #pragma unroll
            for (int q = 0; q < 4; q++) {
                float4 w = Ws4[(q * 64 + u) * AW + k4];
                #pragma unroll
                for (int rr = 0; rr < 4; rr++) {
                    acc[q][rr] = fmaf(w.x, a[rr].x, acc[q][rr]);
                    acc[q][rr] = fmaf(w.y, a[rr].y, acc[q][rr]);
                    acc[q][rr] = fmaf(w.z, a[rr].z, acc[q][rr]);
                    acc[q][rr] = fmaf(w.w, a[rr].w, acc[q][rr]);
                }
            }
        }
        __syncthreads();

        #pragma unroll
        for (int rr = 0; rr < 4; rr++) {
            int row  = rq + 4 * rr;
            float gi = sigf(acc[0][rr] + bi);
            float gf = sigf(acc[1][rr] + bf);
            float gg = tanhg(acc[2][rr] + bg);
            float go = sigf(acc[3][rr] + bo);
            float cn = gf * c[rr] + gi * gg;
            c[rr]    = cn;
            float hn = go * tanhg(cn);
            As[row * K + D_IN + u] = hn;
            ouths[(size_t)t * (BB * HH) + (size_t)(rowbase + row) * HH + u] = hn;
        }
        if (t + 1 < TT && tid < 64) {
            int r = tid >> 2, j = tid & 3;
            As[r * K + j] =
                in[(size_t)(rowbase + r) * (TT * D_IN) + (t + 1) * D_IN + j];
        }
        __syncthreads();
    }
}

// ---------------------------------------------------------------------------
// Layers 1-3 recurrence: K = 64 (h only); xg tile prefetched from GMEM.
// ---------------------------------------------------------------------------
__global__ void __launch_bounds__(256, 1)
lstm_recN(const float4* __restrict__ xg, const float* __restrict__ Whh,
          float* __restrict__ ouths, int write_all) {
    constexpr int K = 64, APAD = 68, AW = 17;
    extern __shared__ float smem[];
    float* Ws = smem;                 // 256*68 (64 used per row)
    float* As = smem + G4 * APAD;     // 16*68 (h in cols 0..63)

    const int tid     = threadIdx.x;
    const int u       = tid & 63;
    const int rq      = tid >> 6;
    const int rowbase = blockIdx.x * 16;

    for (int idx = tid; idx < G4 * K; idx += 256) {
        int g = idx >> 6, k = idx & 63;
        Ws[g * APAD + k] = Whh[idx];
    }
    for (int i = tid; i < 16 * APAD; i += 256) As[i] = 0.0f;
    __syncthreads();

    float c[4] = {0.f, 0.f, 0.f, 0.f};
    const float4* As4 = (const float4*)As;
    const float4* Ws4 = (const float4*)Ws;

    for (int t = 0; t < TT; ++t) {
        // prefetch xg (bias already folded in)
        float4 xgv[4];
        #pragma unroll
        for (int rr = 0; rr < 4; rr++) {
            int row = rq + 4 * rr;
            xgv[rr] = xg[((size_t)t * BB + rowbase + row) * HH + u];
        }

        float acc[4][4];
        #pragma unroll
        for (int q = 0; q < 4; q++)
            #pragma unroll
            for (int rr = 0; rr < 4; rr++) acc[q][rr] = 0.0f;

        #pragma unroll 4
        for (int k4 = 0; k4 < 16; ++k4) {
            float4 a[4];
            #pragma unroll
            for (int rr = 0; rr < 4; rr++) a[rr] = As4[(rq + 4 * rr) * AW + k4];
            #pragma unroll
            for (int q = 0; q < 4; q++) {
                float4 w = Ws4[(q * 64 + u) * AW + k4];
                #pragma unroll
                for (int rr = 0; rr < 4; rr++) {
                    acc[q][rr] = fmaf(w.x, a[rr].x, acc[q][rr]);
                    acc[q][rr] = fmaf(w.y, a[rr].y, acc[q][rr]);
                    acc[q][rr] = fmaf(w.z, a[rr].z, acc[q][rr]);
                    acc[q][rr] = fmaf(w.w, a[rr].w, acc[q][rr]);
                }
            }
        }
        __syncthreads();

        #pragma unroll
        for (int rr = 0; rr < 4; rr++) {
            int row  = rq + 4 * rr;
            float gi = sigf(acc[0][rr] + xgv[rr].x);
            float gf = sigf(acc[1][rr] + xgv[rr].y);
            float gg = tanhg(acc[2][rr] + xgv[rr].z);
            float go = sigf(acc[3][rr] + xgv[rr].w);
            float cn = gf * c[rr] + gi * gg;
            c[rr]    = cn;
            float hn = go * tanhg(cn);
            As[row * APAD + u] = hn;
            if (write_all || t == TT - 1)
                ouths[(size_t)t * (BB * HH) +
                      (size_t)(rowbase + row) * HH + u] = hn;
        }
        __syncthreads();
    }
}

// ---------------------------------------------------------------------------
// Final FC on last timestep of top layer.
// ---------------------------------------------------------------------------
__global__ void fc_kernel(const float* __restrict__ hs,
                          const float* __restrict__ Wfc,
                          const float* __restrict__ bfc,
                          float* __restrict__ out) {
    int idx = blockIdx.x * blockDim.x + threadIdx.x;
    if (idx >= BB * OUTN) return;
    int b = idx / OUTN, o = idx - b * OUTN;
    const float* h = &hs[(size_t)(TT - 1) * (BB * HH) + (size_t)b * HH];
    float s = bfc[o];
    #pragma unroll
    for (int j = 0; j < HH; j++) s = fmaf(h[j], Wfc[o * HH + j], s);
    out[idx] = s;
}

// ---------------------------------------------------------------------------
extern "C" void kernel_launch(void* const* d_in, const int* in_sizes, int n_in,
                              void* d_out, int out_size) {
    const float* x     = (const float*)d_in[0];
    const float* W_ih0 = (const float*)d_in[1];
    const float* W_ihr = (const float*)d_in[2];
    const float* W_hh  = (const float*)d_in[3];
    const float* b_ih  = (const float*)d_in[4];
    const float* b_hh  = (const float*)d_in[5];
    const float* W_fc  = (const float*)d_in[6];
    const float* b_fc  = (const float*)d_in[7];
    float* out = (float*)d_out;

    float *hsA = nullptr, *hsB = nullptr;
    float4* xgp = nullptr;
    float *Whh1 = nullptr, *Wp0 = nullptr, *biasp = nullptr;
    cudaGetSymbolAddress((void**)&hsA, g_hsA);
    cudaGetSymbolAddress((void**)&hsB, g_hsB);
    cudaGetSymbolAddress((void**)&xgp, g_xg);
    cudaGetSymbolAddress((void**)&Whh1, g_Whhsc);
    cudaGetSymbolAddress((void**)&Wp0, g_Wpih);
    cudaGetSymbolAddress((void**)&biasp, g_bias);

    constexpr int SMEM_REC = (G4 + 16) * 68 * 4;           // 73,984 B
    constexpr int SMEM_XG  = HH * G4 * 4 + 32 * HH * 8;    // 81,920 B
    cudaFuncSetAttribute(lstm_rec0,
                         cudaFuncAttributeMaxDynamicSharedMemorySize, SMEM_REC);
    cudaFuncSetAttribute(lstm_recN,
                         cudaFuncAttributeMaxDynamicSharedMemorySize, SMEM_REC);
    cudaFuncSetAttribute(xg_gemm,
                         cudaFuncAttributeMaxDynamicSharedMemorySize, SMEM_XG);

    prep_kernel<<<LL * G4 * 128 / 256, 256>>>(W_ih0, W_ihr, W_hh, b_ih, b_hh);

    // Layer 0 (fused, K=68)
    lstm_rec0<<<BB / 16, 256, SMEM_REC>>>(x, hsA);

    const int xg_grid = (TT * BB) / 32;   // 32768
    float* hs_in  = hsA;
    float* hs_out = hsB;
    for (int l = 1; l < LL; ++l) {
        xg_gemm<<<xg_grid, 256, SMEM_XG>>>(
            hs_in, Wp0 + (size_t)(l - 1) * (HH * G4), biasp + l * G4, xgp);
        lstm_recN<<<BB / 16, 256, SMEM_REC>>>(
            xgp, Whh1 + (size_t)l * (G4 * HH), hs_out, l < LL - 1 ? 1 : 0);
        float* tmp = hs_in; hs_in = hs_out; hs_out = tmp;
    }

    fc_kernel<<<(BB * OUTN + 255) / 256, 256>>>(hs_in, W_fc, b_fc, out);
}

// round 7
// speedup vs baseline: 1.6403x; 1.0098x over previous
#include <cuda_runtime.h>
#include <cstddef>
#include <cstdint>

// Problem constants
#define BB   2048
#define TT   512
#define D_IN 4
#define HH   64
#define LL   4
#define OUTN 5
#define G4   256   // 4*H

#define PLANE ((size_t)TT * BB * HH)   // floats per gate plane

// -------------------------- device scratch --------------------------------
__device__ float g_hsA[(size_t)TT * BB * HH];     // 256 MB ping
__device__ float g_hsB[(size_t)TT * BB * HH];     // 256 MB pong
__device__ float g_xg[4 * PLANE];                 // 1 GB: 4 gate planes [trow][u]
__device__ float g_W0sc[G4 * 68];                 // layer0 combined [gate][68]
__device__ float g_Whhsc[LL][G4 * HH];            // W_hh scalar [gate][64]
__device__ float g_bias[LL][G4];

__device__ __forceinline__ float sigf(float x) {
    return __fdividef(1.0f, 1.0f + __expf(-x));
}
__device__ __forceinline__ float tanhg(float x) {
    return __fdividef(2.0f, 1.0f + __expf(-2.0f * x)) - 1.0f;
}
__device__ __forceinline__ float tf32_rna(float x) {
    float r;
    asm("cvt.rna.tf32.f32 %0, %1;" : "=f"(r) : "f"(x));
    return r;
}

// ---------------------------------------------------------------------------
// Weight prep (layer0 combined, W_hh scalar, fused bias).
// ---------------------------------------------------------------------------
__global__ void prep_kernel(const float* __restrict__ W_ih0,
                            const float* __restrict__ W_hh,
                            const float* __restrict__ b_ih,
                            const float* __restrict__ b_hh) {
    int idx = blockIdx.x * blockDim.x + threadIdx.x;   // l*256*128 + gate*128 + k
    if (idx >= LL * G4 * 128) return;
    int k    = idx & 127;
    int gate = (idx >> 7) & 255;
    int l    = idx >> 15;

    if (k == 0)
        g_bias[l][gate] = b_ih[l * G4 + gate] + b_hh[l * G4 + gate];

    if (l == 0) {
        if (k < D_IN)           g_W0sc[gate * 68 + k] = W_ih0[gate * D_IN + k];
        else if (k < D_IN + HH) g_W0sc[gate * 68 + k] = W_hh[gate * HH + (k - D_IN)];
    } else {
        if (k >= HH) {
            int kk = k - HH;
            g_Whhsc[l][gate * HH + kk] = W_hh[((size_t)l * G4 + gate) * HH + kk];
        }
    }
}

// ====================== mma.sync tf32 xg GEMM ==============================
// xg planes: plane q holds preact of gate block q (+bias) for all rows/units.
//   D[1M,256] = hs[1M,64] x W^T[64,256], 2xTF32 (3 passes: HH, LH, HL).
//   CTA 256 thr = 8 warps: wm = wid&1 (32-row half), wn = wid>>1 (64-col
//   quarter = gate block). Warp tile: 32x64, m16n8k8 frags.

#define XG_GRID   2048
#define XG_TILES  8          // 2048 * 8 * 64 = 1,048,576 rows

#define MMA_TF32(c, a, b) \
    asm volatile("mma.sync.aligned.m16n8k8.row.col.f32.tf32.tf32.f32 " \
        "{%0,%1,%2,%3}, {%4,%5,%6,%7}, {%8,%9}, {%0,%1,%2,%3};" \
        : "+f"((c)[0]), "+f"((c)[1]), "+f"((c)[2]), "+f"((c)[3]) \
        : "r"((a)[0]), "r"((a)[1]), "r"((a)[2]), "r"((a)[3]), \
          "r"((b)[0]), "r"((b)[1]))

// SMEM float offsets (strides padded for conflict-free frag loads)
#define ASTR 68
#define BSTR 264
#define XA_HI 0
#define XA_LO (XA_HI + 64 * ASTR)            // 4352
#define XB_HI (XA_LO + 64 * ASTR)            // 8704
#define XB_LO (XB_HI + 64 * BSTR)            // 25600
#define XG_SMEM_FLOATS (XB_LO + 64 * BSTR)   // 42496 -> 169,984 B

__global__ void __launch_bounds__(256, 1)
xg_mma(const float* __restrict__ hs, const float* __restrict__ Wih,
       const float* __restrict__ bias, float* __restrict__ xgp) {
    extern __shared__ char sm_raw[];
    float* sm = (float*)sm_raw;
    const uint32_t* smu = (const uint32_t*)sm_raw;

    const int tid  = threadIdx.x;
    const int wid  = tid >> 5;
    const int lane = tid & 31;
    const int wm   = wid & 1;         // M half (rows 0-31 / 32-63)
    const int wn   = wid >> 1;        // N quarter = gate block (cols wn*64..+63)
    const int lr   = lane >> 2;       // 0..7
    const int lc   = lane & 3;        // 0..3

    // ---- one-time: W -> B_HI/B_LO smem [k][n], tf32 split ----
    for (int i = tid; i < G4 * HH / 4; i += 256) {      // 4096 float4
        int n = i >> 4, k = (i & 15) * 4;
        float4 v = *(const float4*)&Wih[n * HH + k];    // W[gate n][k..k+3]
        float h0 = tf32_rna(v.x), h1 = tf32_rna(v.y);
        float h2 = tf32_rna(v.z), h3 = tf32_rna(v.w);
        sm[XB_HI + (k + 0) * BSTR + n] = h0;
        sm[XB_HI + (k + 1) * BSTR + n] = h1;
        sm[XB_HI + (k + 2) * BSTR + n] = h2;
        sm[XB_HI + (k + 3) * BSTR + n] = h3;
        sm[XB_LO + (k + 0) * BSTR + n] = tf32_rna(v.x - h0);
        sm[XB_LO + (k + 1) * BSTR + n] = tf32_rna(v.y - h1);
        sm[XB_LO + (k + 2) * BSTR + n] = tf32_rna(v.z - h2);
        sm[XB_LO + (k + 3) * BSTR + n] = tf32_rna(v.w - h3);
    }

    // Bias per output column this thread owns (c0/c1 cols, per n-frag)
    float bias0[8], bias1[8];
    #pragma unroll
    for (int f = 0; f < 8; ++f) {
        int col = wn * 64 + f * 8 + 2 * lc;
        bias0[f] = bias[col];
        bias1[f] = bias[col + 1];
    }

    float* outp = xgp + (size_t)wn * PLANE;   // this warp's gate plane

    for (int it = 0; it < XG_TILES; ++it) {
        size_t row0 = ((size_t)it * XG_GRID + blockIdx.x) * 64;

        __syncthreads();   // previous tile's frag reads done
        // ---- load + split A tile [64 x 64] ----
        #pragma unroll
        for (int i = 0; i < 4; ++i) {
            int idx = tid + i * 256;          // 0..1023 float4
            int row = idx >> 4, k = (idx & 15) * 4;
            float4 v = *(const float4*)&hs[(row0 + row) * HH + k];
            float4 hi, lo;
            hi.x = tf32_rna(v.x); lo.x = tf32_rna(v.x - hi.x);
            hi.y = tf32_rna(v.y); lo.y = tf32_rna(v.y - hi.y);
            hi.z = tf32_rna(v.z); lo.z = tf32_rna(v.z - hi.z);
            hi.w = tf32_rna(v.w); lo.w = tf32_rna(v.w - hi.w);
            *(float4*)&sm[XA_HI + row * ASTR + k] = hi;
            *(float4*)&sm[XA_LO + row * ASTR + k] = lo;
        }
        __syncthreads();

        // ---- accumulators, bias-initialized ----
        float c[2][8][4];
        #pragma unroll
        for (int mm = 0; mm < 2; ++mm)
            #pragma unroll
            for (int f = 0; f < 8; ++f) {
                c[mm][f][0] = bias0[f]; c[mm][f][1] = bias1[f];
                c[mm][f][2] = bias0[f]; c[mm][f][3] = bias1[f];
            }

        // ---- 3 passes x 8 k-chunks ----
        #pragma unroll
        for (int pass = 0; pass < 3; ++pass) {
            const int abase = (pass == 1) ? XA_LO : XA_HI;
            const int bbase = (pass == 2) ? XB_LO : XB_HI;
            #pragma unroll
            for (int kc = 0; kc < 8; ++kc) {
                uint32_t a[2][4];
                #pragma unroll
                for (int mm = 0; mm < 2; ++mm) {
                    int r = wm * 32 + mm * 16 + lr;
                    int k = kc * 8 + lc;
                    a[mm][0] = smu[abase + r * ASTR + k];
                    a[mm][1] = smu[abase + (r + 8) * ASTR + k];
                    a[mm][2] = smu[abase + r * ASTR + k + 4];
                    a[mm][3] = smu[abase + (r + 8) * ASTR + k + 4];
                }
                #pragma unroll
                for (int f = 0; f < 8; ++f) {
                    int n = wn * 64 + f * 8 + lr;
                    int k = kc * 8 + lc;
                    uint32_t b[2];
                    b[0] = smu[bbase + k * BSTR + n];
                    b[1] = smu[bbase + (k + 4) * BSTR + n];
                    MMA_TF32(c[0][f], a[0], b);
                    MMA_TF32(c[1][f], a[1], b);
                }
            }
        }

        // ---- store to gate plane: [row][u], u = n - wn*64 ----
        #pragma unroll
        for (int mm = 0; mm < 2; ++mm) {
            size_t rbase = row0 + wm * 32 + mm * 16 + lr;
            #pragma unroll
            for (int f = 0; f < 8; ++f) {
                int u = f * 8 + 2 * lc;
                *(float2*)&outp[rbase * HH + u] =
                    make_float2(c[mm][f][0], c[mm][f][1]);
                *(float2*)&outp[(rbase + 8) * HH + u] =
                    make_float2(c[mm][f][2], c[mm][f][3]);
            }
        }
    }
}

// ---------------------------------------------------------------------------
// Layer-0 recurrence (proven): K = 68 = [x(4) | h(64)].
// ---------------------------------------------------------------------------
__global__ void __launch_bounds__(256, 1)
lstm_rec0(const float* __restrict__ in, float* __restrict__ ouths) {
    constexpr int K = 68, AW = 17;
    extern __shared__ char sm_raw[];
    float* Ws = (float*)sm_raw;
    float* As = (float*)sm_raw + G4 * K;

    const int tid     = threadIdx.x;
    const int u       = tid & 63;
    const int rq      = tid >> 6;
    const int rowbase = blockIdx.x * 16;

    for (int i = tid; i < G4 * K; i += 256) Ws[i] = g_W0sc[i];
    for (int i = tid; i < 16 * K; i += 256) As[i] = 0.0f;
    __syncthreads();

    const float bi = g_bias[0][u];
    const float bf = g_bias[0][64 + u];
    const float bg = g_bias[0][128 + u];
    const float bo = g_bias[0][192 + u];
    float c[4] = {0.f, 0.f, 0.f, 0.f};

    if (tid < 64) {
        int r = tid >> 2, j = tid & 3;
        As[r * K + j] = in[(size_t)(rowbase + r) * (TT * D_IN) + j];
    }
    __syncthreads();

    const float4* As4 = (const float4*)As;
    const float4* Ws4 = (const float4*)Ws;

    for (int t = 0; t < TT; ++t) {
        float acc[4][4];
        #pragma unroll
        for (int q = 0; q < 4; q++)
            #pragma unroll
            for (int rr = 0; rr < 4; rr++) acc[q][rr] = 0.0f;

        #pragma unroll 4
        for (int k4 = 0; k4 < AW; ++k4) {
            float4 a[4];
            #pragma unroll
            for (int rr = 0; rr < 4; rr++) a[rr] = As4[(rq + 4 * rr) * AW + k4];
            #pragma unroll
            for (int q = 0; q < 4; q++) {
                float4 w = Ws4[(q * 64 + u) * AW + k4];
                #pragma unroll
                for (int rr = 0; rr < 4; rr++) {
                    acc[q][rr] = fmaf(w.x, a[rr].x, acc[q][rr]);
                    acc[q][rr] = fmaf(w.y, a[rr].y, acc[q][rr]);
                    acc[q][rr] = fmaf(w.z, a[rr].z, acc[q][rr]);
                    acc[q][rr] = fmaf(w.w, a[rr].w, acc[q][rr]);
                }
            }
        }
        __syncthreads();

        #pragma unroll
        for (int rr = 0; rr < 4; rr++) {
            int row  = rq + 4 * rr;
            float gi = sigf(acc[0][rr] + bi);
            float gf = sigf(acc[1][rr] + bf);
            float gg = tanhg(acc[2][rr] + bg);
            float go = sigf(acc[3][rr] + bo);
            float cn = gf * c[rr] + gi * gg;
            c[rr]    = cn;
            float hn = go * tanhg(cn);
            As[row * K + D_IN + u] = hn;
            ouths[(size_t)t * (BB * HH) + (size_t)(rowbase + row) * HH + u] = hn;
        }
        if (t + 1 < TT && tid < 64) {
            int r = tid >> 2, j = tid & 3;
            As[r * K + j] =
                in[(size_t)(rowbase + r) * (TT * D_IN) + (t + 1) * D_IN + j];
        }
        __syncthreads();
    }
}

// ---------------------------------------------------------------------------
// Layers 1-3 recurrence (proven): K = 64; xg prefetched from 4 gate planes.
// ---------------------------------------------------------------------------
__global__ void __launch_bounds__(256, 1)
lstm_recN(const float* __restrict__ xgp, const float* __restrict__ Whh,
          float* __restrict__ ouths, int write_all) {
    constexpr int K = 64, APAD = 68, AW = 17;
    extern __shared__ char sm_raw[];
    float* Ws = (float*)sm_raw;
    float* As = (float*)sm_raw + G4 * APAD;

    const int tid     = threadIdx.x;
    const int u       = tid & 63;
    const int rq      = tid >> 6;
    const int rowbase = blockIdx.x * 16;

    const float* xg_i = xgp;
    const float* xg_f = xgp + PLANE;
    const float* xg_g = xgp + 2 * PLANE;
    const float* xg_o = xgp + 3 * PLANE;

    for (int idx = tid; idx < G4 * K; idx += 256) {
        int g = idx >> 6, k = idx & 63;
        Ws[g * APAD + k] = Whh[idx];
    }
    for (int i = tid; i < 16 * APAD; i += 256) As[i] = 0.0f;
    __syncthreads();

    float c[4] = {0.f, 0.f, 0.f, 0.f};
    const float4* As4 = (const float4*)As;
    const float4* Ws4 = (const float4*)Ws;

    for (int t = 0; t < TT; ++t) {
        float xi[4], xf[4], xgv[4], xo[4];
        #pragma unroll
        for (int rr = 0; rr < 4; rr++) {
            size_t off = ((size_t)t * BB + rowbase + rq + 4 * rr) * HH + u;
            xi[rr]  = xg_i[off];
            xf[rr]  = xg_f[off];
            xgv[rr] = xg_g[off];
            xo[rr]  = xg_o[off];
        }

        float acc[4][4];
        #pragma unroll
        for (int q = 0; q < 4; q++)
            #pragma unroll
            for (int rr = 0; rr < 4; rr++) acc[q][rr] = 0.0f;

        #pragma unroll 4
        for (int k4 = 0; k4 < 16; ++k4) {
            float4 a[4];
            #pragma unroll
            for (int rr = 0; rr < 4; rr++) a[rr] = As4[(rq + 4 * rr) * AW + k4];
            #pragma unroll
            for (int q = 0; q < 4; q++) {
                float4 w = Ws4[(q * 64 + u) * AW + k4];
                #pragma unroll
                for (int rr = 0; rr < 4; rr++) {
                    acc[q][rr] = fmaf(w.x, a[rr].x, acc[q][rr]);
                    acc[q][rr] = fmaf(w.y, a[rr].y, acc[q][rr]);
                    acc[q][rr] = fmaf(w.z, a[rr].z, acc[q][rr]);
                    acc[q][rr] = fmaf(w.w, a[rr].w, acc[q][rr]);
                }
            }
        }
        __syncthreads();

        #pragma unroll
        for (int rr = 0; rr < 4; rr++) {
            int row  = rq + 4 * rr;
            float gi = sigf(acc[0][rr] + xi[rr]);
            float gf = sigf(acc[1][rr] + xf[rr]);
            float gg = tanhg(acc[2][rr] + xgv[rr]);
            float go = sigf(acc[3][rr] + xo[rr]);
            float cn = gf * c[rr] + gi * gg;
            c[rr]    = cn;
            float hn = go * tanhg(cn);
            As[row * APAD + u] = hn;
            if (write_all || t == TT - 1)
                ouths[(size_t)t * (BB * HH) +
                      (size_t)(rowbase + row) * HH + u] = hn;
        }
        __syncthreads();
    }
}

// ---------------------------------------------------------------------------
__global__ void fc_kernel(const float* __restrict__ hs,
                          const float* __restrict__ Wfc,
                          const float* __restrict__ bfc,
                          float* __restrict__ out) {
    int idx = blockIdx.x * blockDim.x + threadIdx.x;
    if (idx >= BB * OUTN) return;
    int b = idx / OUTN, o = idx - b * OUTN;
    const float* h = &hs[(size_t)(TT - 1) * (BB * HH) + (size_t)b * HH];
    float s = bfc[o];
    #pragma unroll
    for (int j = 0; j < HH; j++) s = fmaf(h[j], Wfc[o * HH + j], s);
    out[idx] = s;
}

// ---------------------------------------------------------------------------
extern "C" void kernel_launch(void* const* d_in, const int* in_sizes, int n_in,
                              void* d_out, int out_size) {
    const float* x     = (const float*)d_in[0];
    const float* W_ih0 = (const float*)d_in[1];
    const float* W_ihr = (const float*)d_in[2];
    const float* W_hh  = (const float*)d_in[3];
    const float* b_ih  = (const float*)d_in[4];
    const float* b_hh  = (const float*)d_in[5];
    const float* W_fc  = (const float*)d_in[6];
    const float* b_fc  = (const float*)d_in[7];
    float* out = (float*)d_out;

    float *hsA = nullptr, *hsB = nullptr, *xgp = nullptr;
    float *Whh1 = nullptr, *biasp = nullptr;
    cudaGetSymbolAddress((void**)&hsA, g_hsA);
    cudaGetSymbolAddress((void**)&hsB, g_hsB);
    cudaGetSymbolAddress((void**)&xgp, g_xg);
    cudaGetSymbolAddress((void**)&Whh1, g_Whhsc);
    cudaGetSymbolAddress((void**)&biasp, g_bias);

    constexpr int SMEM_REC = (G4 + 16) * 68 * 4;           // 73,984 B
    constexpr int SMEM_XG  = XG_SMEM_FLOATS * 4;           // 169,984 B
    cudaFuncSetAttribute(lstm_rec0,
                         cudaFuncAttributeMaxDynamicSharedMemorySize, SMEM_REC);
    cudaFuncSetAttribute(lstm_recN,
                         cudaFuncAttributeMaxDynamicSharedMemorySize, SMEM_REC);
    cudaFuncSetAttribute(xg_mma,
                         cudaFuncAttributeMaxDynamicSharedMemorySize, SMEM_XG);

    prep_kernel<<<LL * G4 * 128 / 256, 256>>>(W_ih0, W_hh, b_ih, b_hh);

    lstm_rec0<<<BB / 16, 256, SMEM_REC>>>(x, hsA);

    float* hs_in  = hsA;
    float* hs_out = hsB;
    for (int l = 1; l < LL; ++l) {
        xg_mma<<<XG_GRID, 256, SMEM_XG>>>(
            hs_in, W_ihr + (size_t)(l - 1) * (G4 * HH), biasp + l * G4, xgp);
        lstm_recN<<<BB / 16, 256, SMEM_REC>>>(
            xgp, Whh1 + (size_t)l * (G4 * HH), hs_out, l < LL - 1 ? 1 : 0);
        float* tmp = hs_in; hs_in = hs_out; hs_out = tmp;
    }

    fc_kernel<<<(BB * OUTN + 255) / 256, 256>>>(hs_in, W_fc, b_fc, out);
}